// round 13
// baseline (speedup 1.0000x reference)
#include <cuda_runtime.h>
#include <cuda_bf16.h>
#include <mma.h>

using namespace nvcuda;

#define B_NUM 4
#define CNUM  256
#define HWN   4096
#define NH    4
#define HD    64
#define LOG2E 1.4426950408889634f
#define QSCALE (0.125f * LOG2E)
// Schraudolph bf16 exp2 magic: round-to-int bias (2^23+2^22) + 127*128 - 7 (minimax corr)
#define MAGICF 12599161.0f

// ---------------- scratch (device globals; allocation-free rule) ----------
__device__ float g_part [512];
__device__ __nv_bfloat16 g_h [B_NUM * CNUM * HWN];        // GN(x) in bf16, [b][c][pix]
__device__ __nv_bfloat16 g_wqkvb[3 * CNUM * CNUM];        // bf16 weights
__device__ __nv_bfloat16 g_wprojb[CNUM * CNUM];
__device__ __nv_bfloat16 g_qb[B_NUM * NH * HWN * HD];
__device__ __nv_bfloat16 g_kb[B_NUM * NH * HWN * HD];
__device__ __nv_bfloat16 g_vb[B_NUM * NH * HWN * HD];
__device__ __nv_bfloat16 g_ao[B_NUM * HWN * CNUM];        // attention out, bf16

// ---------------- small asm helpers ----------------------------------------
__device__ __forceinline__ unsigned s2u(const void* p) {
    unsigned a;
    asm("{ .reg .u64 t; cvta.to.shared.u64 t, %1; cvt.u32.u64 %0, t; }" : "=r"(a) : "l"(p));
    return a;
}
__device__ __forceinline__ void cpa16(unsigned d, const void* s) {
    asm volatile("cp.async.cg.shared.global [%0], [%1], 16;" :: "r"(d), "l"(s));
}
__device__ __forceinline__ void ldsm4(unsigned* r, unsigned a) {
    asm volatile("ldmatrix.sync.aligned.m8n8.x4.shared.b16 {%0,%1,%2,%3}, [%4];"
        : "=r"(r[0]), "=r"(r[1]), "=r"(r[2]), "=r"(r[3]) : "r"(a));
}
__device__ __forceinline__ void ldsm4t(unsigned* r, unsigned a) {
    asm volatile("ldmatrix.sync.aligned.m8n8.x4.trans.shared.b16 {%0,%1,%2,%3}, [%4];"
        : "=r"(r[0]), "=r"(r[1]), "=r"(r[2]), "=r"(r[3]) : "r"(a));
}
__device__ __forceinline__ void mma_bf(float* c, const unsigned* a, unsigned b0, unsigned b1) {
    asm volatile("mma.sync.aligned.m16n8k16.row.col.f32.bf16.bf16.f32 "
        "{%0,%1,%2,%3}, {%4,%5,%6,%7}, {%8,%9}, {%0,%1,%2,%3};"
        : "+f"(c[0]), "+f"(c[1]), "+f"(c[2]), "+f"(c[3])
        : "r"(a[0]), "r"(a[1]), "r"(a[2]), "r"(a[3]), "r"(b0), "r"(b1));
}
// Schraudolph: t = fma(s,128,MAGIC); low 16 bits of t are bf16(2^s)
__device__ __forceinline__ float ex2t(float s) { return fmaf(s, 128.0f, MAGICF); }
__device__ __forceinline__ float bfval(float t) {
    return __int_as_float(__float_as_int(t) << 16);
}
__device__ __forceinline__ unsigned bfpack(float t0, float t1) {
    return __byte_perm(__float_as_int(t0), __float_as_int(t1), 0x5410);
}
__device__ __forceinline__ unsigned cvtbf2(float lo, float hi) {
    unsigned r; asm("cvt.rn.bf16x2.f32 %0, %1, %2;" : "=r"(r) : "f"(hi), "f"(lo)); return r;
}

// ---------------- kernel 1: groupnorm partial sums -------------------------
__global__ void gn_partial(const float* __restrict__ x) {
    int blk = blockIdx.x;                         // 256 blocks
    const float4* base = (const float4*)x + (size_t)blk * 4096;
    float s = 0.f, s2 = 0.f;
    for (int i = threadIdx.x; i < 4096; i += 256) {
        float4 v = base[i];
        s  += (v.x + v.y) + (v.z + v.w);
        s2 += (v.x*v.x + v.y*v.y) + (v.z*v.z + v.w*v.w);
    }
    __shared__ float r1[256], r2[256];
    r1[threadIdx.x] = s; r2[threadIdx.x] = s2;
    __syncthreads();
    for (int off = 128; off > 0; off >>= 1) {
        if (threadIdx.x < off) {
            r1[threadIdx.x] += r1[threadIdx.x + off];
            r2[threadIdx.x] += r2[threadIdx.x + off];
        }
        __syncthreads();
    }
    if (threadIdx.x == 0) { g_part[blk*2] = r1[0]; g_part[blk*2+1] = r2[0]; }
}

// ---------------- kernel 2: GN apply (inline final) + weight conversion ----
__global__ void gn_apply(const float* __restrict__ x,
                         const float* __restrict__ gamma,
                         const float* __restrict__ beta,
                         const float* __restrict__ wqkv,
                         const float* __restrict__ wproj) {
    int bc = blockIdx.x;
    if (bc < 1024) {                              // GN apply, [b][c]
        int b = bc >> 8, c = bc & 255;
        int bg = b * 8 + (c >> 5);
        __shared__ float sc_s, bi_s;
        if (threadIdx.x == 0) {
            float s = 0.f, s2 = 0.f;
            #pragma unroll
            for (int i = 0; i < 8; i++) { s += g_part[(bg*8+i)*2]; s2 += g_part[(bg*8+i)*2+1]; }
            float mean = s * (1.f/131072.f);
            float var  = s2 * (1.f/131072.f) - mean*mean;
            float rstd = rsqrtf(var + 1e-5f);
            float sc = rstd * gamma[c];
            sc_s = sc;
            bi_s = beta[c] - mean * sc;
        }
        __syncthreads();
        float sc = sc_s, bi = bi_s;
        const float4* src = (const float4*)(x + (size_t)bc * 4096);
        uint2* dst = (uint2*)(g_h + (size_t)bc * 4096);
        for (int i = threadIdx.x; i < 1024; i += 256) {
            float4 v = src[i];
            uint2 o;
            o.x = cvtbf2(fmaf(v.x, sc, bi), fmaf(v.y, sc, bi));
            o.y = cvtbf2(fmaf(v.z, sc, bi), fmaf(v.w, sc, bi));
            dst[i] = o;
        }
    } else {                                      // weight fp32 -> bf16
        int wb = bc - 1024;                       // 0..63, 4096 floats each
        #pragma unroll
        for (int j = 0; j < 4; j++) {
            int idx = wb * 4096 + j * 1024 + threadIdx.x * 4;
            if (idx < 196608) {
                float4 v = *(const float4*)(wqkv + idx);
                uint2 o;
                o.x = cvtbf2(v.x, v.y); o.y = cvtbf2(v.z, v.w);
                *(uint2*)(g_wqkvb + idx) = o;
            } else {
                int p = idx - 196608;
                float4 v = *(const float4*)(wproj + p);
                uint2 o;
                o.x = cvtbf2(v.x, v.y); o.y = cvtbf2(v.z, v.w);
                *(uint2*)(g_wprojb + p) = o;
            }
        }
    }
}

// ---------------- kernel 3: QKV GEMM (A-resident, 12 nt tiles per CTA) -----
// smem: A [256k][72m] bf16 (36864) | B0 B1 [64n][264k] (33792 each) | C 64x68 f32
#define QKV_ASZ (256*72*2)
#define QKV_BSZ (64*264*2)
#define QKV_COFF (QKV_ASZ + 2*QKV_BSZ)
#define QKV_SMEM (QKV_COFF + 64*68*4)   // 121856

__global__ __launch_bounds__(256) void qkv_kernel(const float* __restrict__ bqkv) {
    extern __shared__ char qsm[];
    float* Cs = (float*)(qsm + QKV_COFF);
    int mt = blockIdx.x;     // 0..255 (64-pixel tiles)
    int p0 = mt * 64;
    int b  = p0 >> 12;
    int hw0 = p0 & (HWN - 1);
    int t = threadIdx.x, w = t >> 5, wm = w & 1, wn = w >> 1;
    unsigned su = s2u(qsm);

    // load A once: full K=256, col-major As[k][m] stride 72
    #pragma unroll
    for (int i = 0; i < 8; i++) {
        int e = i * 256 + t;
        int m8 = e & 7, k = e >> 3;
        cpa16(su + (unsigned)(k * 72 + m8 * 8) * 2,
              g_h + (((size_t)(b * CNUM + k)) << 12) + hw0 + m8 * 8);
    }
    asm volatile("cp.async.commit_group;" ::: "memory");

    auto loadB = [&](int nt) {
        unsigned Bu = su + QKV_ASZ + (unsigned)(nt & 1) * QKV_BSZ;
        int o0 = nt * 64;
        #pragma unroll
        for (int i = 0; i < 8; i++) {
            int e = i * 256 + t;
            int k8 = e & 31, n = e >> 5;
            cpa16(Bu + (unsigned)(n * 264 + k8 * 8) * 2,
                  g_wqkvb + (size_t)(o0 + n) * CNUM + k8 * 8);
        }
        asm volatile("cp.async.commit_group;" ::: "memory");
    };

    loadB(0);
    asm volatile("cp.async.wait_group 0;" ::: "memory");
    __syncthreads();

    for (int nt = 0; nt < 12; nt++) {
        if (nt < 11) loadB(nt + 1);
        __nv_bfloat16* As = (__nv_bfloat16*)qsm;
        __nv_bfloat16* Bs = (__nv_bfloat16*)(qsm + QKV_ASZ + (nt & 1) * QKV_BSZ);

        wmma::fragment<wmma::accumulator, 16, 16, 16, float> acc[2];
        #pragma unroll
        for (int i = 0; i < 2; i++) wmma::fill_fragment(acc[i], 0.0f);
        #pragma unroll
        for (int kk = 0; kk < 256; kk += 16) {
            wmma::fragment<wmma::matrix_a, 16, 16, 16, __nv_bfloat16, wmma::col_major> a[2];
            wmma::fragment<wmma::matrix_b, 16, 16, 16, __nv_bfloat16, wmma::col_major> bb;
            #pragma unroll
            for (int i = 0; i < 2; i++)
                wmma::load_matrix_sync(a[i], As + kk * 72 + (wm * 32 + i * 16), 72);
            wmma::load_matrix_sync(bb, Bs + (wn * 16) * 264 + kk, 264);
            #pragma unroll
            for (int i = 0; i < 2; i++)
                wmma::mma_sync(acc[i], a[i], bb, acc[i]);
        }
        #pragma unroll
        for (int i = 0; i < 2; i++)
            wmma::store_matrix_sync(Cs + (wm * 32 + i * 16) * 68 + wn * 16,
                                    acc[i], 68, wmma::mem_row_major);
        __syncthreads();

        int o0 = nt * 64;
        int which = o0 >> 8;            // 0=q,1=k,2=v
        int head  = (o0 >> 6) & 3;
        __nv_bfloat16* dst = (which == 0) ? g_qb : (which == 1) ? g_kb : g_vb;
        float mul = (which == 0) ? QSCALE : 1.0f;
        #pragma unroll
        for (int i = 0; i < 16; i++) {
            int e = i * 256 + t;
            int n = e & 63, m = e >> 6;
            float v = (Cs[m * 68 + n] + bqkv[o0 + n]) * mul;
            dst[(((size_t)((b * NH + head) * HWN + hw0 + m)) << 6) + n] = __float2bfloat16(v);
        }
        if (nt < 11) asm volatile("cp.async.wait_group 0;" ::: "memory");
        __syncthreads();   // C reuse + B(nt+1) visible + B(nt) fully consumed
    }
}

// ---------------- kernel 4: attention (FA2, Schraudolph bf16 exp2) ---------
// grid (32, 16). 128 threads, 4 warps x 32 q-rows. (R9 version, 2 CTAs/SM)
__global__ __launch_bounds__(128, 2) void attn_kernel() {
    extern __shared__ __align__(16) char dsm[];
    const int SP = 72;
    int t = threadIdx.x;
    int w = t >> 5, l = t & 31;
    int qb = blockIdx.x, bh = blockIdx.y;
    int q0 = qb * 128;
    const __nv_bfloat16* qp = g_qb + (size_t)bh * HWN * HD + (size_t)q0 * HD;
    const __nv_bfloat16* kp = g_kb + (size_t)bh * HWN * HD;
    const __nv_bfloat16* vp = g_vb + (size_t)bh * HWN * HD;

    unsigned su = s2u(dsm);
    unsigned Qs = su;
    unsigned KB0 = su + 128 * SP * 2;
    unsigned KB1 = KB0 + 64 * SP * 2;
    unsigned VB0 = KB1 + 64 * SP * 2;
    unsigned VB1 = VB0 + 64 * SP * 2;

    {
        #pragma unroll
        for (int i = 0; i < 4; i++) {
            int c = i * 128 + t;
            int row = c >> 3, col8 = c & 7;
            unsigned so = (unsigned)(row * SP + col8 * 8) * 2;
            cpa16(KB0 + so, kp + (size_t)row * 64 + col8 * 8);
            cpa16(VB0 + so, vp + (size_t)row * 64 + col8 * 8);
        }
        asm volatile("cp.async.commit_group;" ::: "memory");
    }
    #pragma unroll
    for (int i = 0; i < 8; i++) {
        int c = i * 128 + t;
        int row = c >> 3, col8 = c & 7;
        *(uint4*)(dsm + (size_t)(row * SP + col8 * 8) * 2) =
            *(const uint4*)(qp + (size_t)row * 64 + col8 * 8);
    }
    __syncthreads();

    int lrow_a = l & 15,  lcol_a = (l >> 4) * 8;
    int lrow_k = (l & 7) + ((l >> 4) << 3), lcol_k = ((l >> 3) & 1) * 8;
    int r0 = w * 32;

    unsigned qf[2][4][4];
    #pragma unroll
    for (int mb = 0; mb < 2; mb++)
        #pragma unroll
        for (int kc = 0; kc < 4; kc++)
            ldsm4(qf[mb][kc],
                  Qs + (unsigned)(((r0 + mb*16 + lrow_a) * SP + kc*16 + lcol_a) * 2));

    float oacc[2][8][4];
    #pragma unroll
    for (int mb = 0; mb < 2; mb++)
        #pragma unroll
        for (int j = 0; j < 8; j++)
            #pragma unroll
            for (int i = 0; i < 4; i++) oacc[mb][j][i] = 0.f;
    float rs[4] = {0.f, 0.f, 0.f, 0.f};

    for (int kb = 0; kb < 64; kb++) {
        asm volatile("cp.async.wait_group 0;" ::: "memory");
        __syncthreads();
        if (kb + 1 < 64) {
            int k0 = (kb + 1) * 64;
            unsigned kd = ((kb + 1) & 1) ? KB1 : KB0;
            unsigned vd = ((kb + 1) & 1) ? VB1 : VB0;
            #pragma unroll
            for (int i = 0; i < 4; i++) {
                int c = i * 128 + t;
                int row = c >> 3, col8 = c & 7;
                unsigned so = (unsigned)(row * SP + col8 * 8) * 2;
                cpa16(kd + so, kp + (size_t)(k0 + row) * 64 + col8 * 8);
                cpa16(vd + so, vp + (size_t)(k0 + row) * 64 + col8 * 8);
            }
            asm volatile("cp.async.commit_group;" ::: "memory");
        }
        unsigned kS = (kb & 1) ? KB1 : KB0;
        unsigned vS = (kb & 1) ? VB1 : VB0;

        unsigned pf[2][4][4];
        #pragma unroll
        for (int ph = 0; ph < 2; ph++) {
            float s[2][2][2][4];
            #pragma unroll
            for (int g2 = 0; g2 < 2; g2++)
                #pragma unroll
                for (int mb = 0; mb < 2; mb++)
                    #pragma unroll
                    for (int h = 0; h < 2; h++)
                        #pragma unroll
                        for (int i = 0; i < 4; i++) s[g2][mb][h][i] = 0.f;
            #pragma unroll
            for (int kc = 0; kc < 4; kc++) {
                #pragma unroll
                for (int g2 = 0; g2 < 2; g2++) {
                    int g = ph * 2 + g2;
                    unsigned bb[4];
                    ldsm4(bb, kS + (unsigned)(((g*16 + lrow_k) * SP + kc*16 + lcol_k) * 2));
                    mma_bf(s[g2][0][0], qf[0][kc], bb[0], bb[1]);
                    mma_bf(s[g2][0][1], qf[0][kc], bb[2], bb[3]);
                    mma_bf(s[g2][1][0], qf[1][kc], bb[0], bb[1]);
                    mma_bf(s[g2][1][1], qf[1][kc], bb[2], bb[3]);
                }
            }
            #pragma unroll
            for (int g2 = 0; g2 < 2; g2++) {
                int g = ph * 2 + g2;
                #pragma unroll
                for (int mb = 0; mb < 2; mb++) {
                    float e0 = ex2t(s[g2][mb][0][0]), e1 = ex2t(s[g2][mb][0][1]);
                    float e2 = ex2t(s[g2][mb][0][2]), e3 = ex2t(s[g2][mb][0][3]);
                    float f0 = ex2t(s[g2][mb][1][0]), f1 = ex2t(s[g2][mb][1][1]);
                    float f2 = ex2t(s[g2][mb][1][2]), f3 = ex2t(s[g2][mb][1][3]);
                    pf[mb][g][0] = bfpack(e0, e1);
                    pf[mb][g][1] = bfpack(e2, e3);
                    pf[mb][g][2] = bfpack(f0, f1);
                    pf[mb][g][3] = bfpack(f2, f3);
                    rs[mb*2+0] += (bfval(e0) + bfval(e1)) + (bfval(f0) + bfval(f1));
                    rs[mb*2+1] += (bfval(e2) + bfval(e3)) + (bfval(f2) + bfval(f3));
                }
            }
        }
        #pragma unroll
        for (int g = 0; g < 4; g++) {
            #pragma unroll
            for (int dg = 0; dg < 4; dg++) {
                unsigned vv[4];
                ldsm4t(vv, vS + (unsigned)(((g*16 + lrow_a) * SP + dg*16 + lcol_a) * 2));
                mma_bf(oacc[0][2*dg],   pf[0][g], vv[0], vv[1]);
                mma_bf(oacc[0][2*dg+1], pf[0][g], vv[2], vv[3]);
                mma_bf(oacc[1][2*dg],   pf[1][g], vv[0], vv[1]);
                mma_bf(oacc[1][2*dg+1], pf[1][g], vv[2], vv[3]);
            }
        }
    }

    #pragma unroll
    for (int i = 0; i < 4; i++) {
        rs[i] += __shfl_xor_sync(0xffffffffu, rs[i], 1);
        rs[i] += __shfl_xor_sync(0xffffffffu, rs[i], 2);
    }
    int b = bh >> 2, h = bh & 3;
    __nv_bfloat16* aop = g_ao + ((size_t)b * HWN + q0) * CNUM + h * HD;
    #pragma unroll
    for (int mb = 0; mb < 2; mb++) {
        float i0 = 1.0f / rs[mb*2], i1 = 1.0f / rs[mb*2+1];
        int row0 = r0 + mb*16 + (l >> 2);
        int cbase = (l & 3) * 2;
        #pragma unroll
        for (int j = 0; j < 8; j++) {
            *(unsigned*)(aop + (size_t)row0 * CNUM + j*8 + cbase) =
                cvtbf2(oacc[mb][j][0] * i0, oacc[mb][j][1] * i0);
            *(unsigned*)(aop + (size_t)(row0 + 8) * CNUM + j*8 + cbase) =
                cvtbf2(oacc[mb][j][2] * i1, oacc[mb][j][3] * i1);
        }
    }
}

// ---------------- kernel 5: proj GEMM + residual (A-resident) --------------
// smem: A [64m][264k] bf16 (33792) | B0 B1 [64n][264k] (33792 each) | C 64x68 f32
#define PROJ_ASZ (64*264*2)
#define PROJ_COFF (3*PROJ_ASZ)
#define PROJ_SMEM (PROJ_COFF + 64*68*4)   // 118784

__global__ __launch_bounds__(256) void proj_kernel(const float* __restrict__ x,
                                                   const float* __restrict__ bproj,
                                                   float* __restrict__ out) {
    extern __shared__ char psm[];
    float* Cs = (float*)(psm + PROJ_COFF);
    int mt = blockIdx.x;     // 0..255
    int p0 = mt * 64;
    int b  = p0 >> 12;
    int hw0 = p0 & (HWN - 1);
    int t = threadIdx.x, w = t >> 5, wm = w & 1, wn = w >> 1;
    unsigned su = s2u(psm);

    // load A once: rows m of g_ao, full K=256, row-major stride 264
    #pragma unroll
    for (int i = 0; i < 8; i++) {
        int e = i * 256 + t;
        int k8 = e & 31, m = e >> 5;
        cpa16(su + (unsigned)(m * 264 + k8 * 8) * 2,
              g_ao + ((size_t)(p0 + m)) * CNUM + k8 * 8);
    }
    asm volatile("cp.async.commit_group;" ::: "memory");

    auto loadB = [&](int nt) {
        unsigned Bu = su + PROJ_ASZ + (unsigned)(1 + (nt & 1)) * 0 + PROJ_ASZ * (nt & 1);
        Bu = su + PROJ_ASZ + (unsigned)(nt & 1) * PROJ_ASZ;
        int o0 = nt * 64;
        #pragma unroll
        for (int i = 0; i < 8; i++) {
            int e = i * 256 + t;
            int k8 = e & 31, n = e >> 5;
            cpa16(Bu + (unsigned)(n * 264 + k8 * 8) * 2,
                  g_wprojb + (size_t)(o0 + n) * CNUM + k8 * 8);
        }
        asm volatile("cp.async.commit_group;" ::: "memory");
    };

    loadB(0);
    asm volatile("cp.async.wait_group 0;" ::: "memory");
    __syncthreads();

    for (int nt = 0; nt < 4; nt++) {
        if (nt < 3) loadB(nt + 1);
        __nv_bfloat16* As = (__nv_bfloat16*)psm;
        __nv_bfloat16* Bs = (__nv_bfloat16*)(psm + PROJ_ASZ + (nt & 1) * PROJ_ASZ);

        wmma::fragment<wmma::accumulator, 16, 16, 16, float> acc[2];
        #pragma unroll
        for (int i = 0; i < 2; i++) wmma::fill_fragment(acc[i], 0.0f);
        #pragma unroll
        for (int kk = 0; kk < 256; kk += 16) {
            wmma::fragment<wmma::matrix_a, 16, 16, 16, __nv_bfloat16, wmma::row_major> a[2];
            wmma::fragment<wmma::matrix_b, 16, 16, 16, __nv_bfloat16, wmma::col_major> bb;
            #pragma unroll
            for (int i = 0; i < 2; i++)
                wmma::load_matrix_sync(a[i], As + (wm * 32 + i * 16) * 264 + kk, 264);
            wmma::load_matrix_sync(bb, Bs + (wn * 16) * 264 + kk, 264);
            #pragma unroll
            for (int i = 0; i < 2; i++)
                wmma::mma_sync(acc[i], a[i], bb, acc[i]);
        }
        #pragma unroll
        for (int i = 0; i < 2; i++)
            wmma::store_matrix_sync(Cs + (wm * 32 + i * 16) * 68 + wn * 16,
                                    acc[i], 68, wmma::mem_row_major);
        __syncthreads();

        int o0 = nt * 64;
        #pragma unroll
        for (int i = 0; i < 16; i++) {
            int e = i * 256 + t;
            int m = e & 63, n = e >> 6;
            size_t oidx = (((size_t)(b * CNUM + o0 + n)) << 12) + hw0 + m;
            out[oidx] = x[oidx] + Cs[m * 68 + n] + bproj[o0 + n];
        }
        if (nt < 3) asm volatile("cp.async.wait_group 0;" ::: "memory");
        __syncthreads();
    }
}

// ---------------- launch ----------------------------------------------------
extern "C" void kernel_launch(void* const* d_in, const int* in_sizes, int n_in,
                              void* d_out, int out_size) {
    const float* x      = (const float*)d_in[0];
    const float* gamma  = (const float*)d_in[1];
    const float* beta   = (const float*)d_in[2];
    const float* w_qkv  = (const float*)d_in[3];
    const float* b_qkv  = (const float*)d_in[4];
    const float* w_proj = (const float*)d_in[5];
    const float* b_proj = (const float*)d_in[6];
    float* out = (float*)d_out;

    gn_partial<<<256, 256>>>(x);
    gn_apply<<<1088, 256>>>(x, gamma, beta, w_qkv, w_proj);

    cudaFuncSetAttribute(qkv_kernel, cudaFuncAttributeMaxDynamicSharedMemorySize, QKV_SMEM);
    qkv_kernel<<<256, 256, QKV_SMEM>>>(b_qkv);

    const int attn_smem = (128 + 4 * 64) * 72 * 2;   // 55296 B
    cudaFuncSetAttribute(attn_kernel, cudaFuncAttributeMaxDynamicSharedMemorySize, attn_smem);
    attn_kernel<<<dim3(32, 16), 128, attn_smem>>>();

    cudaFuncSetAttribute(proj_kernel, cudaFuncAttributeMaxDynamicSharedMemorySize, PROJ_SMEM);
    proj_kernel<<<256, 256, PROJ_SMEM>>>(x, b_proj, out);
}

// round 14
// speedup vs baseline: 1.1083x; 1.1083x over previous
#include <cuda_runtime.h>
#include <cuda_bf16.h>
#include <mma.h>

using namespace nvcuda;

#define B_NUM 4
#define CNUM  256
#define HWN   4096
#define NH    4
#define HD    64
#define LOG2E 1.4426950408889634f
#define QSCALE (0.125f * LOG2E)
// Schraudolph bf16 exp2 magic: round-to-int bias (2^23+2^22) + 127*128 - 7 (minimax corr)
#define MAGICF 12599161.0f

// ---------------- scratch (device globals; allocation-free rule) ----------
__device__ float g_part [512];
__device__ __nv_bfloat16 g_h [B_NUM * CNUM * HWN];        // GN(x) in bf16, [b][c][pix]
__device__ __nv_bfloat16 g_wqkvb[3 * CNUM * CNUM];        // bf16 weights
__device__ __nv_bfloat16 g_wprojb[CNUM * CNUM];
__device__ __nv_bfloat16 g_qb[B_NUM * NH * HWN * HD];
__device__ __nv_bfloat16 g_kb[B_NUM * NH * HWN * HD];
__device__ __nv_bfloat16 g_vb[B_NUM * NH * HWN * HD];
__device__ __nv_bfloat16 g_ao[B_NUM * HWN * CNUM];        // attention out, bf16

// ---------------- small asm helpers ----------------------------------------
__device__ __forceinline__ unsigned s2u(const void* p) {
    unsigned a;
    asm("{ .reg .u64 t; cvta.to.shared.u64 t, %1; cvt.u32.u64 %0, t; }" : "=r"(a) : "l"(p));
    return a;
}
__device__ __forceinline__ void cpa16(unsigned d, const void* s) {
    asm volatile("cp.async.cg.shared.global [%0], [%1], 16;" :: "r"(d), "l"(s));
}
__device__ __forceinline__ void ldsm4(unsigned* r, unsigned a) {
    asm volatile("ldmatrix.sync.aligned.m8n8.x4.shared.b16 {%0,%1,%2,%3}, [%4];"
        : "=r"(r[0]), "=r"(r[1]), "=r"(r[2]), "=r"(r[3]) : "r"(a));
}
__device__ __forceinline__ void ldsm4t(unsigned* r, unsigned a) {
    asm volatile("ldmatrix.sync.aligned.m8n8.x4.trans.shared.b16 {%0,%1,%2,%3}, [%4];"
        : "=r"(r[0]), "=r"(r[1]), "=r"(r[2]), "=r"(r[3]) : "r"(a));
}
__device__ __forceinline__ void mma_bf(float* c, const unsigned* a, unsigned b0, unsigned b1) {
    asm volatile("mma.sync.aligned.m16n8k16.row.col.f32.bf16.bf16.f32 "
        "{%0,%1,%2,%3}, {%4,%5,%6,%7}, {%8,%9}, {%0,%1,%2,%3};"
        : "+f"(c[0]), "+f"(c[1]), "+f"(c[2]), "+f"(c[3])
        : "r"(a[0]), "r"(a[1]), "r"(a[2]), "r"(a[3]), "r"(b0), "r"(b1));
}
// Schraudolph: t = fma(s,128,MAGIC); low 16 bits of t are bf16(2^s)
__device__ __forceinline__ float ex2t(float s) { return fmaf(s, 128.0f, MAGICF); }
__device__ __forceinline__ float bfval(float t) {
    return __int_as_float(__float_as_int(t) << 16);
}
__device__ __forceinline__ unsigned bfpack(float t0, float t1) {
    return __byte_perm(__float_as_int(t0), __float_as_int(t1), 0x5410);
}
__device__ __forceinline__ unsigned cvtbf2(float lo, float hi) {
    unsigned r; asm("cvt.rn.bf16x2.f32 %0, %1, %2;" : "=r"(r) : "f"(hi), "f"(lo)); return r;
}

// ---------------- kernel 1: groupnorm partial sums -------------------------
__global__ void gn_partial(const float* __restrict__ x) {
    int blk = blockIdx.x;                         // 256 blocks
    const float4* base = (const float4*)x + (size_t)blk * 4096;
    float s = 0.f, s2 = 0.f;
    for (int i = threadIdx.x; i < 4096; i += 256) {
        float4 v = base[i];
        s  += (v.x + v.y) + (v.z + v.w);
        s2 += (v.x*v.x + v.y*v.y) + (v.z*v.z + v.w*v.w);
    }
    __shared__ float r1[256], r2[256];
    r1[threadIdx.x] = s; r2[threadIdx.x] = s2;
    __syncthreads();
    for (int off = 128; off > 0; off >>= 1) {
        if (threadIdx.x < off) {
            r1[threadIdx.x] += r1[threadIdx.x + off];
            r2[threadIdx.x] += r2[threadIdx.x + off];
        }
        __syncthreads();
    }
    if (threadIdx.x == 0) { g_part[blk*2] = r1[0]; g_part[blk*2+1] = r2[0]; }
}

// ---------------- kernel 2: GN apply (inline final stats) + weight conv ----
__global__ void gn_apply(const float* __restrict__ x,
                         const float* __restrict__ gamma,
                         const float* __restrict__ beta,
                         const float* __restrict__ wqkv,
                         const float* __restrict__ wproj) {
    int bc = blockIdx.x;
    if (bc < 1024) {                              // GN apply, [b][c]
        int b = bc >> 8, c = bc & 255;
        int bg = b * 8 + (c >> 5);
        __shared__ float sc_s, bi_s;
        if (threadIdx.x == 0) {
            float s = 0.f, s2 = 0.f;
            #pragma unroll
            for (int i = 0; i < 8; i++) { s += g_part[(bg*8+i)*2]; s2 += g_part[(bg*8+i)*2+1]; }
            float mean = s * (1.f/131072.f);
            float var  = s2 * (1.f/131072.f) - mean*mean;
            float rstd = rsqrtf(var + 1e-5f);
            float sc = rstd * gamma[c];
            sc_s = sc;
            bi_s = beta[c] - mean * sc;
        }
        __syncthreads();
        float sc = sc_s, bi = bi_s;
        const float4* src = (const float4*)(x + (size_t)bc * 4096);
        uint2* dst = (uint2*)(g_h + (size_t)bc * 4096);
        for (int i = threadIdx.x; i < 1024; i += 256) {
            float4 v = src[i];
            uint2 o;
            o.x = cvtbf2(fmaf(v.x, sc, bi), fmaf(v.y, sc, bi));
            o.y = cvtbf2(fmaf(v.z, sc, bi), fmaf(v.w, sc, bi));
            dst[i] = o;
        }
    } else {                                      // weight fp32 -> bf16
        int wb = bc - 1024;                       // 0..63, 4096 floats each
        #pragma unroll
        for (int j = 0; j < 4; j++) {
            int idx = wb * 4096 + j * 1024 + threadIdx.x * 4;
            if (idx < 196608) {
                float4 v = *(const float4*)(wqkv + idx);
                uint2 o;
                o.x = cvtbf2(v.x, v.y); o.y = cvtbf2(v.z, v.w);
                *(uint2*)(g_wqkvb + idx) = o;
            } else {
                int p = idx - 196608;
                float4 v = *(const float4*)(wproj + p);
                uint2 o;
                o.x = cvtbf2(v.x, v.y); o.y = cvtbf2(v.z, v.w);
                *(uint2*)(g_wprojb + p) = o;
            }
        }
    }
}

// ---------------- kernel 3: QKV GEMM (bf16 in, 128x64 tiles, 256 thr) ------
#define QKV_AS_STRIDE 136
#define QKV_SMEM (64*136*2 + 64*72*2 + 128*68*4)   // 61440

__global__ __launch_bounds__(256) void qkv_kernel(const float* __restrict__ bqkv) {
    extern __shared__ char qsm[];
    __nv_bfloat16* As = (__nv_bfloat16*)qsm;                      // [64][136] col-major
    __nv_bfloat16* Bs = (__nv_bfloat16*)(qsm + 64*136*2);         // [64][72]
    float*         Cs = (float*)(qsm + 64*136*2 + 64*72*2);       // [128][68]
    int nt = blockIdx.x;     // 0..11
    int mt = blockIdx.y;     // 0..127
    int p0 = mt * 128;
    int b  = p0 >> 12;
    int hw0 = p0 & (HWN - 1);
    int o0 = nt * 64;
    int t = threadIdx.x, w = t >> 5, wm = w & 3, wn = w >> 2;

    wmma::fragment<wmma::accumulator, 16, 16, 16, float> acc[2][2];
    #pragma unroll
    for (int i = 0; i < 2; i++)
        #pragma unroll
        for (int j = 0; j < 2; j++) wmma::fill_fragment(acc[i][j], 0.0f);

    for (int kt = 0; kt < 4; kt++) {
        int c0 = kt * 64;
        __syncthreads();
        #pragma unroll
        for (int i = 0; i < 4; i++) {
            int e = i * 256 + t;
            int m8 = e & 15, k = e >> 4;
            *(uint4*)(As + k * QKV_AS_STRIDE + m8 * 8) =
                *(const uint4*)(g_h + (((size_t)(b * CNUM + c0 + k)) << 12) + hw0 + m8 * 8);
        }
        #pragma unroll
        for (int i = 0; i < 2; i++) {
            int e = i * 256 + t;
            int k8 = e & 7, n = e >> 3;
            *(uint4*)(Bs + n * 72 + k8 * 8) =
                *(const uint4*)(g_wqkvb + (size_t)(o0 + n) * CNUM + c0 + k8 * 8);
        }
        __syncthreads();
        #pragma unroll
        for (int kk = 0; kk < 64; kk += 16) {
            wmma::fragment<wmma::matrix_a, 16, 16, 16, __nv_bfloat16, wmma::col_major> a[2];
            wmma::fragment<wmma::matrix_b, 16, 16, 16, __nv_bfloat16, wmma::col_major> bb[2];
            #pragma unroll
            for (int i = 0; i < 2; i++)
                wmma::load_matrix_sync(a[i], As + kk * QKV_AS_STRIDE + (wm * 32 + i * 16), QKV_AS_STRIDE);
            #pragma unroll
            for (int j = 0; j < 2; j++)
                wmma::load_matrix_sync(bb[j], Bs + (wn * 32 + j * 16) * 72 + kk, 72);
            #pragma unroll
            for (int i = 0; i < 2; i++)
                #pragma unroll
                for (int j = 0; j < 2; j++)
                    wmma::mma_sync(acc[i][j], a[i], bb[j], acc[i][j]);
        }
    }
    __syncthreads();
    #pragma unroll
    for (int i = 0; i < 2; i++)
        #pragma unroll
        for (int j = 0; j < 2; j++)
            wmma::store_matrix_sync(Cs + (wm * 32 + i * 16) * 68 + (wn * 32 + j * 16),
                                    acc[i][j], 68, wmma::mem_row_major);
    __syncthreads();
    int which = o0 >> 8;                // 0=q,1=k,2=v
    int head  = (o0 >> 6) & 3;
    __nv_bfloat16* dst = (which == 0) ? g_qb : (which == 1) ? g_kb : g_vb;
    float mul = (which == 0) ? QSCALE : 1.0f;
    #pragma unroll
    for (int i = 0; i < 32; i++) {
        int e = i * 256 + t;
        int n = e & 63, m = e >> 6;
        float v = (Cs[m * 68 + n] + bqkv[o0 + n]) * mul;
        dst[(((size_t)((b * NH + head) * HWN + hw0 + m)) << 6) + n] = __float2bfloat16(v);
    }
}

// ---------------- kernel 4: attention (FA2, Schraudolph bf16 exp2) ---------
// grid (32, 16). 128 threads, 4 warps x 32 q-rows. (R8/R9 version, 2 CTAs/SM)
__global__ __launch_bounds__(128, 2) void attn_kernel() {
    extern __shared__ __align__(16) char dsm[];
    const int SP = 72;
    int t = threadIdx.x;
    int w = t >> 5, l = t & 31;
    int qb = blockIdx.x, bh = blockIdx.y;
    int q0 = qb * 128;
    const __nv_bfloat16* qp = g_qb + (size_t)bh * HWN * HD + (size_t)q0 * HD;
    const __nv_bfloat16* kp = g_kb + (size_t)bh * HWN * HD;
    const __nv_bfloat16* vp = g_vb + (size_t)bh * HWN * HD;

    unsigned su = s2u(dsm);
    unsigned Qs = su;
    unsigned KB0 = su + 128 * SP * 2;
    unsigned KB1 = KB0 + 64 * SP * 2;
    unsigned VB0 = KB1 + 64 * SP * 2;
    unsigned VB1 = VB0 + 64 * SP * 2;

    {
        #pragma unroll
        for (int i = 0; i < 4; i++) {
            int c = i * 128 + t;
            int row = c >> 3, col8 = c & 7;
            unsigned so = (unsigned)(row * SP + col8 * 8) * 2;
            cpa16(KB0 + so, kp + (size_t)row * 64 + col8 * 8);
            cpa16(VB0 + so, vp + (size_t)row * 64 + col8 * 8);
        }
        asm volatile("cp.async.commit_group;" ::: "memory");
    }
    #pragma unroll
    for (int i = 0; i < 8; i++) {
        int c = i * 128 + t;
        int row = c >> 3, col8 = c & 7;
        *(uint4*)(dsm + (size_t)(row * SP + col8 * 8) * 2) =
            *(const uint4*)(qp + (size_t)row * 64 + col8 * 8);
    }
    __syncthreads();

    int lrow_a = l & 15,  lcol_a = (l >> 4) * 8;
    int lrow_k = (l & 7) + ((l >> 4) << 3), lcol_k = ((l >> 3) & 1) * 8;
    int r0 = w * 32;

    unsigned qf[2][4][4];
    #pragma unroll
    for (int mb = 0; mb < 2; mb++)
        #pragma unroll
        for (int kc = 0; kc < 4; kc++)
            ldsm4(qf[mb][kc],
                  Qs + (unsigned)(((r0 + mb*16 + lrow_a) * SP + kc*16 + lcol_a) * 2));

    float oacc[2][8][4];
    #pragma unroll
    for (int mb = 0; mb < 2; mb++)
        #pragma unroll
        for (int j = 0; j < 8; j++)
            #pragma unroll
            for (int i = 0; i < 4; i++) oacc[mb][j][i] = 0.f;
    float rs[4] = {0.f, 0.f, 0.f, 0.f};

    for (int kb = 0; kb < 64; kb++) {
        asm volatile("cp.async.wait_group 0;" ::: "memory");
        __syncthreads();
        if (kb + 1 < 64) {
            int k0 = (kb + 1) * 64;
            unsigned kd = ((kb + 1) & 1) ? KB1 : KB0;
            unsigned vd = ((kb + 1) & 1) ? VB1 : VB0;
            #pragma unroll
            for (int i = 0; i < 4; i++) {
                int c = i * 128 + t;
                int row = c >> 3, col8 = c & 7;
                unsigned so = (unsigned)(row * SP + col8 * 8) * 2;
                cpa16(kd + so, kp + (size_t)(k0 + row) * 64 + col8 * 8);
                cpa16(vd + so, vp + (size_t)(k0 + row) * 64 + col8 * 8);
            }
            asm volatile("cp.async.commit_group;" ::: "memory");
        }
        unsigned kS = (kb & 1) ? KB1 : KB0;
        unsigned vS = (kb & 1) ? VB1 : VB0;

        unsigned pf[2][4][4];
        #pragma unroll
        for (int ph = 0; ph < 2; ph++) {
            float s[2][2][2][4];
            #pragma unroll
            for (int g2 = 0; g2 < 2; g2++)
                #pragma unroll
                for (int mb = 0; mb < 2; mb++)
                    #pragma unroll
                    for (int h = 0; h < 2; h++)
                        #pragma unroll
                        for (int i = 0; i < 4; i++) s[g2][mb][h][i] = 0.f;
            #pragma unroll
            for (int kc = 0; kc < 4; kc++) {
                #pragma unroll
                for (int g2 = 0; g2 < 2; g2++) {
                    int g = ph * 2 + g2;
                    unsigned bb[4];
                    ldsm4(bb, kS + (unsigned)(((g*16 + lrow_k) * SP + kc*16 + lcol_k) * 2));
                    mma_bf(s[g2][0][0], qf[0][kc], bb[0], bb[1]);
                    mma_bf(s[g2][0][1], qf[0][kc], bb[2], bb[3]);
                    mma_bf(s[g2][1][0], qf[1][kc], bb[0], bb[1]);
                    mma_bf(s[g2][1][1], qf[1][kc], bb[2], bb[3]);
                }
            }
            #pragma unroll
            for (int g2 = 0; g2 < 2; g2++) {
                int g = ph * 2 + g2;
                #pragma unroll
                for (int mb = 0; mb < 2; mb++) {
                    float e0 = ex2t(s[g2][mb][0][0]), e1 = ex2t(s[g2][mb][0][1]);
                    float e2 = ex2t(s[g2][mb][0][2]), e3 = ex2t(s[g2][mb][0][3]);
                    float f0 = ex2t(s[g2][mb][1][0]), f1 = ex2t(s[g2][mb][1][1]);
                    float f2 = ex2t(s[g2][mb][1][2]), f3 = ex2t(s[g2][mb][1][3]);
                    pf[mb][g][0] = bfpack(e0, e1);
                    pf[mb][g][1] = bfpack(e2, e3);
                    pf[mb][g][2] = bfpack(f0, f1);
                    pf[mb][g][3] = bfpack(f2, f3);
                    rs[mb*2+0] += (bfval(e0) + bfval(e1)) + (bfval(f0) + bfval(f1));
                    rs[mb*2+1] += (bfval(e2) + bfval(e3)) + (bfval(f2) + bfval(f3));
                }
            }
        }
        #pragma unroll
        for (int g = 0; g < 4; g++) {
            #pragma unroll
            for (int dg = 0; dg < 4; dg++) {
                unsigned vv[4];
                ldsm4t(vv, vS + (unsigned)(((g*16 + lrow_a) * SP + dg*16 + lcol_a) * 2));
                mma_bf(oacc[0][2*dg],   pf[0][g], vv[0], vv[1]);
                mma_bf(oacc[0][2*dg+1], pf[0][g], vv[2], vv[3]);
                mma_bf(oacc[1][2*dg],   pf[1][g], vv[0], vv[1]);
                mma_bf(oacc[1][2*dg+1], pf[1][g], vv[2], vv[3]);
            }
        }
    }

    #pragma unroll
    for (int i = 0; i < 4; i++) {
        rs[i] += __shfl_xor_sync(0xffffffffu, rs[i], 1);
        rs[i] += __shfl_xor_sync(0xffffffffu, rs[i], 2);
    }
    int b = bh >> 2, h = bh & 3;
    __nv_bfloat16* aop = g_ao + ((size_t)b * HWN + q0) * CNUM + h * HD;
    #pragma unroll
    for (int mb = 0; mb < 2; mb++) {
        float i0 = 1.0f / rs[mb*2], i1 = 1.0f / rs[mb*2+1];
        int row0 = r0 + mb*16 + (l >> 2);
        int cbase = (l & 3) * 2;
        #pragma unroll
        for (int j = 0; j < 8; j++) {
            *(unsigned*)(aop + (size_t)row0 * CNUM + j*8 + cbase) =
                cvtbf2(oacc[mb][j][0] * i0, oacc[mb][j][1] * i0);
            *(unsigned*)(aop + (size_t)(row0 + 8) * CNUM + j*8 + cbase) =
                cvtbf2(oacc[mb][j][2] * i1, oacc[mb][j][3] * i1);
        }
    }
}

// ---------------- kernel 5: proj GEMM + residual (bf16 in, 256 thr) --------
#define PROJ_SMEM (128*72*2 + 64*72*2 + 128*68*4)   // 62464

__global__ __launch_bounds__(256) void proj_kernel(const float* __restrict__ x,
                                                   const float* __restrict__ bproj,
                                                   float* __restrict__ out) {
    extern __shared__ char psm[];
    __nv_bfloat16* As = (__nv_bfloat16*)psm;                      // [128][72] row-major
    __nv_bfloat16* Bs = (__nv_bfloat16*)(psm + 128*72*2);         // [64][72]
    float*         Cs = (float*)(psm + 128*72*2 + 64*72*2);       // [128][68]
    int nt = blockIdx.x;     // 0..3
    int mt = blockIdx.y;     // 0..127
    int p0 = mt * 128;
    int b  = p0 >> 12;
    int hw0 = p0 & (HWN - 1);
    int o0 = nt * 64;
    int t = threadIdx.x, w = t >> 5, wm = w & 3, wn = w >> 2;

    wmma::fragment<wmma::accumulator, 16, 16, 16, float> acc[2][2];
    #pragma unroll
    for (int i = 0; i < 2; i++)
        #pragma unroll
        for (int j = 0; j < 2; j++) wmma::fill_fragment(acc[i][j], 0.0f);

    for (int kt = 0; kt < 4; kt++) {
        int c0 = kt * 64;
        __syncthreads();
        #pragma unroll
        for (int i = 0; i < 4; i++) {
            int e = i * 256 + t;
            int k8 = e & 7, m = e >> 3;
            *(uint4*)(As + m * 72 + k8 * 8) =
                *(const uint4*)(g_ao + ((size_t)(p0 + m)) * CNUM + c0 + k8 * 8);
        }
        #pragma unroll
        for (int i = 0; i < 2; i++) {
            int e = i * 256 + t;
            int k8 = e & 7, n = e >> 3;
            *(uint4*)(Bs + n * 72 + k8 * 8) =
                *(const uint4*)(g_wprojb + (size_t)(o0 + n) * CNUM + c0 + k8 * 8);
        }
        __syncthreads();
        #pragma unroll
        for (int kk = 0; kk < 64; kk += 16) {
            wmma::fragment<wmma::matrix_a, 16, 16, 16, __nv_bfloat16, wmma::row_major> a[2];
            wmma::fragment<wmma::matrix_b, 16, 16, 16, __nv_bfloat16, wmma::col_major> bb[2];
            #pragma unroll
            for (int i = 0; i < 2; i++)
                wmma::load_matrix_sync(a[i], As + (wm * 32 + i * 16) * 72 + kk, 72);
            #pragma unroll
            for (int j = 0; j < 2; j++)
                wmma::load_matrix_sync(bb[j], Bs + (wn * 32 + j * 16) * 72 + kk, 72);
            #pragma unroll
            for (int i = 0; i < 2; i++)
                #pragma unroll
                for (int j = 0; j < 2; j++)
                    wmma::mma_sync(acc[i][j], a[i], bb[j], acc[i][j]);
        }
    }
    __syncthreads();
    #pragma unroll
    for (int i = 0; i < 2; i++)
        #pragma unroll
        for (int j = 0; j < 2; j++)
            wmma::store_matrix_sync(Cs + (wm * 32 + i * 16) * 68 + (wn * 32 + j * 16),
                                    acc[i][j], 68, wmma::mem_row_major);
    __syncthreads();
    #pragma unroll
    for (int i = 0; i < 32; i++) {
        int e = i * 256 + t;
        int m = e & 127, n = e >> 7;
        size_t oidx = (((size_t)(b * CNUM + o0 + n)) << 12) + hw0 + m;
        out[oidx] = x[oidx] + Cs[m * 68 + n] + bproj[o0 + n];
    }
}

// ---------------- launch ----------------------------------------------------
extern "C" void kernel_launch(void* const* d_in, const int* in_sizes, int n_in,
                              void* d_out, int out_size) {
    const float* x      = (const float*)d_in[0];
    const float* gamma  = (const float*)d_in[1];
    const float* beta   = (const float*)d_in[2];
    const float* w_qkv  = (const float*)d_in[3];
    const float* b_qkv  = (const float*)d_in[4];
    const float* w_proj = (const float*)d_in[5];
    const float* b_proj = (const float*)d_in[6];
    float* out = (float*)d_out;

    gn_partial<<<256, 256>>>(x);
    gn_apply<<<1088, 256>>>(x, gamma, beta, w_qkv, w_proj);

    cudaFuncSetAttribute(qkv_kernel, cudaFuncAttributeMaxDynamicSharedMemorySize, QKV_SMEM);
    qkv_kernel<<<dim3(12, 128), 256, QKV_SMEM>>>(b_qkv);

    const int attn_smem = (128 + 4 * 64) * 72 * 2;   // 55296 B
    cudaFuncSetAttribute(attn_kernel, cudaFuncAttributeMaxDynamicSharedMemorySize, attn_smem);
    attn_kernel<<<dim3(32, 16), 128, attn_smem>>>();

    cudaFuncSetAttribute(proj_kernel, cudaFuncAttributeMaxDynamicSharedMemorySize, PROJ_SMEM);
    proj_kernel<<<dim3(4, 128), 256, PROJ_SMEM>>>(x, b_proj, out);
}

// round 15
// speedup vs baseline: 1.1551x; 1.0422x over previous
#include <cuda_runtime.h>
#include <cuda_bf16.h>
#include <mma.h>

using namespace nvcuda;

#define B_NUM 4
#define CNUM  256
#define HWN   4096
#define NH    4
#define HD    64
#define LOG2E 1.4426950408889634f
#define QSCALE (0.125f * LOG2E)
// Schraudolph bf16 exp2 magic: round-to-int bias (2^23+2^22) + 127*128 - 7 (minimax corr)
#define MAGICF 12599161.0f

// ---------------- scratch (device globals; allocation-free rule) ----------
__device__ float g_part [512];
__device__ __nv_bfloat16 g_h [B_NUM * CNUM * HWN];        // GN(x) in bf16, [b][c][pix]
__device__ __nv_bfloat16 g_wqkvb[3 * CNUM * CNUM];        // bf16 weights
__device__ __nv_bfloat16 g_wprojb[CNUM * CNUM];
__device__ __nv_bfloat16 g_qb[B_NUM * NH * HWN * HD];
__device__ __nv_bfloat16 g_kb[B_NUM * NH * HWN * HD];
__device__ __nv_bfloat16 g_vb[B_NUM * NH * HWN * HD];
__device__ __nv_bfloat16 g_ao[B_NUM * HWN * CNUM];        // attention out, bf16

// ---------------- small asm helpers ----------------------------------------
__device__ __forceinline__ unsigned s2u(const void* p) {
    unsigned a;
    asm("{ .reg .u64 t; cvta.to.shared.u64 t, %1; cvt.u32.u64 %0, t; }" : "=r"(a) : "l"(p));
    return a;
}
__device__ __forceinline__ void cpa16(unsigned d, const void* s) {
    asm volatile("cp.async.cg.shared.global [%0], [%1], 16;" :: "r"(d), "l"(s));
}
__device__ __forceinline__ void ldsm4(unsigned* r, unsigned a) {
    asm volatile("ldmatrix.sync.aligned.m8n8.x4.shared.b16 {%0,%1,%2,%3}, [%4];"
        : "=r"(r[0]), "=r"(r[1]), "=r"(r[2]), "=r"(r[3]) : "r"(a));
}
__device__ __forceinline__ void ldsm4t(unsigned* r, unsigned a) {
    asm volatile("ldmatrix.sync.aligned.m8n8.x4.trans.shared.b16 {%0,%1,%2,%3}, [%4];"
        : "=r"(r[0]), "=r"(r[1]), "=r"(r[2]), "=r"(r[3]) : "r"(a));
}
__device__ __forceinline__ void mma_bf(float* c, const unsigned* a, unsigned b0, unsigned b1) {
    asm volatile("mma.sync.aligned.m16n8k16.row.col.f32.bf16.bf16.f32 "
        "{%0,%1,%2,%3}, {%4,%5,%6,%7}, {%8,%9}, {%0,%1,%2,%3};"
        : "+f"(c[0]), "+f"(c[1]), "+f"(c[2]), "+f"(c[3])
        : "r"(a[0]), "r"(a[1]), "r"(a[2]), "r"(a[3]), "r"(b0), "r"(b1));
}
// Schraudolph: t = fma(s,128,MAGIC); low 16 bits of t are bf16(2^s)
__device__ __forceinline__ float ex2t(float s) { return fmaf(s, 128.0f, MAGICF); }
__device__ __forceinline__ float bfval(float t) {
    return __int_as_float(__float_as_int(t) << 16);
}
__device__ __forceinline__ unsigned bfpack(float t0, float t1) {
    return __byte_perm(__float_as_int(t0), __float_as_int(t1), 0x5410);
}
__device__ __forceinline__ unsigned cvtbf2(float lo, float hi) {
    unsigned r; asm("cvt.rn.bf16x2.f32 %0, %1, %2;" : "=r"(r) : "f"(hi), "f"(lo)); return r;
}

// ---------------- kernel 1: groupnorm partial sums -------------------------
__global__ void gn_partial(const float* __restrict__ x) {
    int blk = blockIdx.x;                         // 256 blocks
    const float4* base = (const float4*)x + (size_t)blk * 4096;
    float s = 0.f, s2 = 0.f;
    for (int i = threadIdx.x; i < 4096; i += 256) {
        float4 v = base[i];
        s  += (v.x + v.y) + (v.z + v.w);
        s2 += (v.x*v.x + v.y*v.y) + (v.z*v.z + v.w*v.w);
    }
    __shared__ float r1[256], r2[256];
    r1[threadIdx.x] = s; r2[threadIdx.x] = s2;
    __syncthreads();
    for (int off = 128; off > 0; off >>= 1) {
        if (threadIdx.x < off) {
            r1[threadIdx.x] += r1[threadIdx.x + off];
            r2[threadIdx.x] += r2[threadIdx.x + off];
        }
        __syncthreads();
    }
    if (threadIdx.x == 0) { g_part[blk*2] = r1[0]; g_part[blk*2+1] = r2[0]; }
}

// ---------------- kernel 2: GN apply (inline final stats) + weight conv ----
__global__ void gn_apply(const float* __restrict__ x,
                         const float* __restrict__ gamma,
                         const float* __restrict__ beta,
                         const float* __restrict__ wqkv,
                         const float* __restrict__ wproj) {
    int bc = blockIdx.x;
    if (bc < 1024) {                              // GN apply, [b][c]
        int b = bc >> 8, c = bc & 255;
        int bg = b * 8 + (c >> 5);
        __shared__ float sc_s, bi_s;
        if (threadIdx.x == 0) {
            float s = 0.f, s2 = 0.f;
            #pragma unroll
            for (int i = 0; i < 8; i++) { s += g_part[(bg*8+i)*2]; s2 += g_part[(bg*8+i)*2+1]; }
            float mean = s * (1.f/131072.f);
            float var  = s2 * (1.f/131072.f) - mean*mean;
            float rstd = rsqrtf(var + 1e-5f);
            float sc = rstd * gamma[c];
            sc_s = sc;
            bi_s = beta[c] - mean * sc;
        }
        __syncthreads();
        float sc = sc_s, bi = bi_s;
        const float4* src = (const float4*)(x + (size_t)bc * 4096);
        uint2* dst = (uint2*)(g_h + (size_t)bc * 4096);
        for (int i = threadIdx.x; i < 1024; i += 256) {
            float4 v = src[i];
            uint2 o;
            o.x = cvtbf2(fmaf(v.x, sc, bi), fmaf(v.y, sc, bi));
            o.y = cvtbf2(fmaf(v.z, sc, bi), fmaf(v.w, sc, bi));
            dst[i] = o;
        }
    } else {                                      // weight fp32 -> bf16
        int wb = bc - 1024;                       // 0..63, 4096 floats each
        #pragma unroll
        for (int j = 0; j < 4; j++) {
            int idx = wb * 4096 + j * 1024 + threadIdx.x * 4;
            if (idx < 196608) {
                float4 v = *(const float4*)(wqkv + idx);
                uint2 o;
                o.x = cvtbf2(v.x, v.y); o.y = cvtbf2(v.z, v.w);
                *(uint2*)(g_wqkvb + idx) = o;
            } else {
                int p = idx - 196608;
                float4 v = *(const float4*)(wproj + p);
                uint2 o;
                o.x = cvtbf2(v.x, v.y); o.y = cvtbf2(v.z, v.w);
                *(uint2*)(g_wprojb + p) = o;
            }
        }
    }
}

// ---------------- kernel 3: QKV GEMM (128x128 tiles, C aliased, 2-pass) ----
// smem union: [ As 64x136 bf16 (17408) | Bs 128x72 bf16 (18432) ]  (35840 B)
//             [ Cs 128x68 f32 (34816, aliased at base, used after MMAs) ]
#define QKV_AS_ST 136
#define QKV_BOFF  17408
#define QKV_SMEM  35840

__global__ __launch_bounds__(256) void qkv_kernel(const float* __restrict__ bqkv) {
    extern __shared__ char qsm[];
    __nv_bfloat16* As = (__nv_bfloat16*)qsm;                 // [64k][136m]
    __nv_bfloat16* Bs = (__nv_bfloat16*)(qsm + QKV_BOFF);    // [128n][72k]
    float*         Cs = (float*)qsm;                         // [128m][68] (alias)
    int nt = blockIdx.x;     // 0..5 (128 output channels)
    int mt = blockIdx.y;     // 0..127
    int p0 = mt * 128;
    int b  = p0 >> 12;
    int hw0 = p0 & (HWN - 1);
    int o0 = nt * 128;
    int t = threadIdx.x, w = t >> 5, wm = w & 3, wn = w >> 2;

    wmma::fragment<wmma::accumulator, 16, 16, 16, float> acc[2][4];
    #pragma unroll
    for (int i = 0; i < 2; i++)
        #pragma unroll
        for (int j = 0; j < 4; j++) wmma::fill_fragment(acc[i][j], 0.0f);

    for (int kt = 0; kt < 4; kt++) {
        int c0 = kt * 64;
        __syncthreads();
        // A: 64 k-rows x 128 m (16B copies of bf16 h)
        #pragma unroll
        for (int i = 0; i < 4; i++) {
            int e = i * 256 + t;
            int m8 = e & 15, k = e >> 4;
            *(uint4*)(As + k * QKV_AS_ST + m8 * 8) =
                *(const uint4*)(g_h + (((size_t)(b * CNUM + c0 + k)) << 12) + hw0 + m8 * 8);
        }
        // B: 128 n x 64 k
        #pragma unroll
        for (int i = 0; i < 4; i++) {
            int e = i * 256 + t;
            int k8 = e & 7, n = e >> 3;
            *(uint4*)(Bs + n * 72 + k8 * 8) =
                *(const uint4*)(g_wqkvb + (size_t)(o0 + n) * CNUM + c0 + k8 * 8);
        }
        __syncthreads();
        #pragma unroll
        for (int kk = 0; kk < 64; kk += 16) {
            wmma::fragment<wmma::matrix_a, 16, 16, 16, __nv_bfloat16, wmma::col_major> a[2];
            wmma::fragment<wmma::matrix_b, 16, 16, 16, __nv_bfloat16, wmma::col_major> bb[4];
            #pragma unroll
            for (int i = 0; i < 2; i++)
                wmma::load_matrix_sync(a[i], As + kk * QKV_AS_ST + (wm * 32 + i * 16), QKV_AS_ST);
            #pragma unroll
            for (int j = 0; j < 4; j++)
                wmma::load_matrix_sync(bb[j], Bs + (wn * 64 + j * 16) * 72 + kk, 72);
            #pragma unroll
            for (int i = 0; i < 2; i++)
                #pragma unroll
                for (int j = 0; j < 4; j++)
                    wmma::mma_sync(acc[i][j], a[i], bb[j], acc[i][j]);
        }
    }
    // two-pass epilogue: pass p covers output cols [o0+64p, o0+64p+64)
    #pragma unroll
    for (int p = 0; p < 2; p++) {
        __syncthreads();              // MMAs (or prior pass reads) done before C write
        if (wn == p) {
            #pragma unroll
            for (int i = 0; i < 2; i++)
                #pragma unroll
                for (int j = 0; j < 4; j++)
                    wmma::store_matrix_sync(Cs + (wm * 32 + i * 16) * 68 + j * 16,
                                            acc[i][j], 68, wmma::mem_row_major);
        }
        __syncthreads();
        int o0p = o0 + p * 64;
        int which = o0p >> 8;            // 0=q,1=k,2=v
        int head  = (o0p >> 6) & 3;
        __nv_bfloat16* dst = (which == 0) ? g_qb : (which == 1) ? g_kb : g_vb;
        float mul = (which == 0) ? QSCALE : 1.0f;
        #pragma unroll
        for (int i = 0; i < 16; i++) {
            int e = i * 256 + t;          // 4096 bf16x2 pairs
            int n2 = e & 31, m = e >> 5;
            float v0 = (Cs[m * 68 + n2*2]     + bqkv[o0p + n2*2])     * mul;
            float v1 = (Cs[m * 68 + n2*2 + 1] + bqkv[o0p + n2*2 + 1]) * mul;
            *(unsigned*)(dst + (((size_t)((b * NH + head) * HWN + hw0 + m)) << 6) + n2*2) =
                cvtbf2(v0, v1);
        }
    }
}

// ---------------- kernel 4: attention (FA2, Schraudolph bf16 exp2) ---------
// grid (32, 16). 128 threads, 4 warps x 32 q-rows. (R8/R9 version, 2 CTAs/SM)
__global__ __launch_bounds__(128, 2) void attn_kernel() {
    extern __shared__ __align__(16) char dsm[];
    const int SP = 72;
    int t = threadIdx.x;
    int w = t >> 5, l = t & 31;
    int qb = blockIdx.x, bh = blockIdx.y;
    int q0 = qb * 128;
    const __nv_bfloat16* qp = g_qb + (size_t)bh * HWN * HD + (size_t)q0 * HD;
    const __nv_bfloat16* kp = g_kb + (size_t)bh * HWN * HD;
    const __nv_bfloat16* vp = g_vb + (size_t)bh * HWN * HD;

    unsigned su = s2u(dsm);
    unsigned Qs = su;
    unsigned KB0 = su + 128 * SP * 2;
    unsigned KB1 = KB0 + 64 * SP * 2;
    unsigned VB0 = KB1 + 64 * SP * 2;
    unsigned VB1 = VB0 + 64 * SP * 2;

    {
        #pragma unroll
        for (int i = 0; i < 4; i++) {
            int c = i * 128 + t;
            int row = c >> 3, col8 = c & 7;
            unsigned so = (unsigned)(row * SP + col8 * 8) * 2;
            cpa16(KB0 + so, kp + (size_t)row * 64 + col8 * 8);
            cpa16(VB0 + so, vp + (size_t)row * 64 + col8 * 8);
        }
        asm volatile("cp.async.commit_group;" ::: "memory");
    }
    #pragma unroll
    for (int i = 0; i < 8; i++) {
        int c = i * 128 + t;
        int row = c >> 3, col8 = c & 7;
        *(uint4*)(dsm + (size_t)(row * SP + col8 * 8) * 2) =
            *(const uint4*)(qp + (size_t)row * 64 + col8 * 8);
    }
    __syncthreads();

    int lrow_a = l & 15,  lcol_a = (l >> 4) * 8;
    int lrow_k = (l & 7) + ((l >> 4) << 3), lcol_k = ((l >> 3) & 1) * 8;
    int r0 = w * 32;

    unsigned qf[2][4][4];
    #pragma unroll
    for (int mb = 0; mb < 2; mb++)
        #pragma unroll
        for (int kc = 0; kc < 4; kc++)
            ldsm4(qf[mb][kc],
                  Qs + (unsigned)(((r0 + mb*16 + lrow_a) * SP + kc*16 + lcol_a) * 2));

    float oacc[2][8][4];
    #pragma unroll
    for (int mb = 0; mb < 2; mb++)
        #pragma unroll
        for (int j = 0; j < 8; j++)
            #pragma unroll
            for (int i = 0; i < 4; i++) oacc[mb][j][i] = 0.f;
    float rs[4] = {0.f, 0.f, 0.f, 0.f};

    for (int kb = 0; kb < 64; kb++) {
        asm volatile("cp.async.wait_group 0;" ::: "memory");
        __syncthreads();
        if (kb + 1 < 64) {
            int k0 = (kb + 1) * 64;
            unsigned kd = ((kb + 1) & 1) ? KB1 : KB0;
            unsigned vd = ((kb + 1) & 1) ? VB1 : VB0;
            #pragma unroll
            for (int i = 0; i < 4; i++) {
                int c = i * 128 + t;
                int row = c >> 3, col8 = c & 7;
                unsigned so = (unsigned)(row * SP + col8 * 8) * 2;
                cpa16(kd + so, kp + (size_t)(k0 + row) * 64 + col8 * 8);
                cpa16(vd + so, vp + (size_t)(k0 + row) * 64 + col8 * 8);
            }
            asm volatile("cp.async.commit_group;" ::: "memory");
        }
        unsigned kS = (kb & 1) ? KB1 : KB0;
        unsigned vS = (kb & 1) ? VB1 : VB0;

        unsigned pf[2][4][4];
        #pragma unroll
        for (int ph = 0; ph < 2; ph++) {
            float s[2][2][2][4];
            #pragma unroll
            for (int g2 = 0; g2 < 2; g2++)
                #pragma unroll
                for (int mb = 0; mb < 2; mb++)
                    #pragma unroll
                    for (int h = 0; h < 2; h++)
                        #pragma unroll
                        for (int i = 0; i < 4; i++) s[g2][mb][h][i] = 0.f;
            #pragma unroll
            for (int kc = 0; kc < 4; kc++) {
                #pragma unroll
                for (int g2 = 0; g2 < 2; g2++) {
                    int g = ph * 2 + g2;
                    unsigned bb[4];
                    ldsm4(bb, kS + (unsigned)(((g*16 + lrow_k) * SP + kc*16 + lcol_k) * 2));
                    mma_bf(s[g2][0][0], qf[0][kc], bb[0], bb[1]);
                    mma_bf(s[g2][0][1], qf[0][kc], bb[2], bb[3]);
                    mma_bf(s[g2][1][0], qf[1][kc], bb[0], bb[1]);
                    mma_bf(s[g2][1][1], qf[1][kc], bb[2], bb[3]);
                }
            }
            #pragma unroll
            for (int g2 = 0; g2 < 2; g2++) {
                int g = ph * 2 + g2;
                #pragma unroll
                for (int mb = 0; mb < 2; mb++) {
                    float e0 = ex2t(s[g2][mb][0][0]), e1 = ex2t(s[g2][mb][0][1]);
                    float e2 = ex2t(s[g2][mb][0][2]), e3 = ex2t(s[g2][mb][0][3]);
                    float f0 = ex2t(s[g2][mb][1][0]), f1 = ex2t(s[g2][mb][1][1]);
                    float f2 = ex2t(s[g2][mb][1][2]), f3 = ex2t(s[g2][mb][1][3]);
                    pf[mb][g][0] = bfpack(e0, e1);
                    pf[mb][g][1] = bfpack(e2, e3);
                    pf[mb][g][2] = bfpack(f0, f1);
                    pf[mb][g][3] = bfpack(f2, f3);
                    rs[mb*2+0] += (bfval(e0) + bfval(e1)) + (bfval(f0) + bfval(f1));
                    rs[mb*2+1] += (bfval(e2) + bfval(e3)) + (bfval(f2) + bfval(f3));
                }
            }
        }
        #pragma unroll
        for (int g = 0; g < 4; g++) {
            #pragma unroll
            for (int dg = 0; dg < 4; dg++) {
                unsigned vv[4];
                ldsm4t(vv, vS + (unsigned)(((g*16 + lrow_a) * SP + dg*16 + lcol_a) * 2));
                mma_bf(oacc[0][2*dg],   pf[0][g], vv[0], vv[1]);
                mma_bf(oacc[0][2*dg+1], pf[0][g], vv[2], vv[3]);
                mma_bf(oacc[1][2*dg],   pf[1][g], vv[0], vv[1]);
                mma_bf(oacc[1][2*dg+1], pf[1][g], vv[2], vv[3]);
            }
        }
    }

    #pragma unroll
    for (int i = 0; i < 4; i++) {
        rs[i] += __shfl_xor_sync(0xffffffffu, rs[i], 1);
        rs[i] += __shfl_xor_sync(0xffffffffu, rs[i], 2);
    }
    int b = bh >> 2, h = bh & 3;
    __nv_bfloat16* aop = g_ao + ((size_t)b * HWN + q0) * CNUM + h * HD;
    #pragma unroll
    for (int mb = 0; mb < 2; mb++) {
        float i0 = 1.0f / rs[mb*2], i1 = 1.0f / rs[mb*2+1];
        int row0 = r0 + mb*16 + (l >> 2);
        int cbase = (l & 3) * 2;
        #pragma unroll
        for (int j = 0; j < 8; j++) {
            *(unsigned*)(aop + (size_t)row0 * CNUM + j*8 + cbase) =
                cvtbf2(oacc[mb][j][0] * i0, oacc[mb][j][1] * i0);
            *(unsigned*)(aop + (size_t)(row0 + 8) * CNUM + j*8 + cbase) =
                cvtbf2(oacc[mb][j][2] * i1, oacc[mb][j][3] * i1);
        }
    }
}

// ---------------- kernel 5: proj GEMM + residual (128x128, aliased C) ------
// smem union: [ As 128x72 bf16 (18432) | Bs 128x72 bf16 (18432) ]  (36864 B)
//             [ Cs 128x68 f32 (34816, aliased at base) ]
#define PROJ_BOFF 18432
#define PROJ_SMEM 36864

__global__ __launch_bounds__(256) void proj_kernel(const float* __restrict__ x,
                                                   const float* __restrict__ bproj,
                                                   float* __restrict__ out) {
    extern __shared__ char psm[];
    __nv_bfloat16* As = (__nv_bfloat16*)psm;                  // [128m][72k]
    __nv_bfloat16* Bs = (__nv_bfloat16*)(psm + PROJ_BOFF);    // [128n][72k]
    float*         Cs = (float*)psm;                          // [128m][68] (alias)
    int nt = blockIdx.x;     // 0..1
    int mt = blockIdx.y;     // 0..127
    int p0 = mt * 128;
    int b  = p0 >> 12;
    int hw0 = p0 & (HWN - 1);
    int o0 = nt * 128;
    int t = threadIdx.x, w = t >> 5, wm = w & 3, wn = w >> 2;

    wmma::fragment<wmma::accumulator, 16, 16, 16, float> acc[2][4];
    #pragma unroll
    for (int i = 0; i < 2; i++)
        #pragma unroll
        for (int j = 0; j < 4; j++) wmma::fill_fragment(acc[i][j], 0.0f);

    for (int kt = 0; kt < 4; kt++) {
        int c0 = kt * 64;
        __syncthreads();
        #pragma unroll
        for (int i = 0; i < 4; i++) {
            int e = i * 256 + t;
            int k8 = e & 7, m = e >> 3;
            *(uint4*)(As + m * 72 + k8 * 8) =
                *(const uint4*)(g_ao + ((size_t)(p0 + m)) * CNUM + c0 + k8 * 8);
        }
        #pragma unroll
        for (int i = 0; i < 4; i++) {
            int e = i * 256 + t;
            int k8 = e & 7, n = e >> 3;
            *(uint4*)(Bs + n * 72 + k8 * 8) =
                *(const uint4*)(g_wprojb + (size_t)(o0 + n) * CNUM + c0 + k8 * 8);
        }
        __syncthreads();
        #pragma unroll
        for (int kk = 0; kk < 64; kk += 16) {
            wmma::fragment<wmma::matrix_a, 16, 16, 16, __nv_bfloat16, wmma::row_major> a[2];
            wmma::fragment<wmma::matrix_b, 16, 16, 16, __nv_bfloat16, wmma::col_major> bb[4];
            #pragma unroll
            for (int i = 0; i < 2; i++)
                wmma::load_matrix_sync(a[i], As + (wm * 32 + i * 16) * 72 + kk, 72);
            #pragma unroll
            for (int j = 0; j < 4; j++)
                wmma::load_matrix_sync(bb[j], Bs + (wn * 64 + j * 16) * 72 + kk, 72);
            #pragma unroll
            for (int i = 0; i < 2; i++)
                #pragma unroll
                for (int j = 0; j < 4; j++)
                    wmma::mma_sync(acc[i][j], a[i], bb[j], acc[i][j]);
        }
    }
    // two-pass epilogue
    #pragma unroll
    for (int p = 0; p < 2; p++) {
        __syncthreads();
        if (wn == p) {
            #pragma unroll
            for (int i = 0; i < 2; i++)
                #pragma unroll
                for (int j = 0; j < 4; j++)
                    wmma::store_matrix_sync(Cs + (wm * 32 + i * 16) * 68 + j * 16,
                                            acc[i][j], 68, wmma::mem_row_major);
        }
        __syncthreads();
        int o0p = o0 + p * 64;
        #pragma unroll
        for (int i = 0; i < 32; i++) {
            int e = i * 256 + t;
            int m = e & 127, n = e >> 7;
            size_t oidx = (((size_t)(b * CNUM + o0p + n)) << 12) + hw0 + m;
            out[oidx] = x[oidx] + Cs[m * 68 + n] + bproj[o0p + n];
        }
    }
}

// ---------------- launch ----------------------------------------------------
extern "C" void kernel_launch(void* const* d_in, const int* in_sizes, int n_in,
                              void* d_out, int out_size) {
    const float* x      = (const float*)d_in[0];
    const float* gamma  = (const float*)d_in[1];
    const float* beta   = (const float*)d_in[2];
    const float* w_qkv  = (const float*)d_in[3];
    const float* b_qkv  = (const float*)d_in[4];
    const float* w_proj = (const float*)d_in[5];
    const float* b_proj = (const float*)d_in[6];
    float* out = (float*)d_out;

    gn_partial<<<256, 256>>>(x);
    gn_apply<<<1088, 256>>>(x, gamma, beta, w_qkv, w_proj);

    cudaFuncSetAttribute(qkv_kernel, cudaFuncAttributeMaxDynamicSharedMemorySize, QKV_SMEM);
    qkv_kernel<<<dim3(6, 128), 256, QKV_SMEM>>>(b_qkv);

    const int attn_smem = (128 + 4 * 64) * 72 * 2;   // 55296 B
    cudaFuncSetAttribute(attn_kernel, cudaFuncAttributeMaxDynamicSharedMemorySize, attn_smem);
    attn_kernel<<<dim3(32, 16), 128, attn_smem>>>();

    cudaFuncSetAttribute(proj_kernel, cudaFuncAttributeMaxDynamicSharedMemorySize, PROJ_SMEM);
    proj_kernel<<<dim3(2, 128), 256, PROJ_SMEM>>>(x, b_proj, out);
}